// round 10
// baseline (speedup 1.0000x reference)
#include <cuda_runtime.h>
#include <cuda_bf16.h>
#include <cstdint>

// ---------------------------------------------------------------------------
// HeteroSAGEAttention on GB300 — round 10: int8 2-limb IMMA GEMMs.
// mma.sync.m16n8k32.s8 does 2x MACs/instruction vs bf16 k16 -> mainloop mma
// count halves (384 -> 192 per warp-tile-equivalent).
// A: per-row scale, 2 limbs (qh + ql/256). B: per-col scale, 2 limbs.
// acc1 = sum qh*ph ; acc2 = sum(ql*ph + qh*pl);  y = sa*sb*(256*acc1+acc2)/256
// CSR + fused agg + stream schedule + register prefetch: validated r4-r9.
// ---------------------------------------------------------------------------

#define NMAX   100000
#define EMAX   500000
#define HDIM   128
#define LEAK   0.2f
#define EPS_C  1e-6f

// ------------------------- scratch (__device__ globals) --------------------
__device__ float g_A  [NMAX * HDIM];
__device__ float g_B  [NMAX * HDIM];
__device__ float g_C  [NMAX * HDIM];
__device__ float g_D  [NMAX * HDIM];
__device__ float g_A2 [NMAX * HDIM];
__device__ float g_B2 [NMAX * HDIM];
__device__ float g_C2 [NMAX * HDIM];
__device__ float g_D2 [NMAX * HDIM];
__device__ float g_xu1[NMAX * HDIM];
__device__ float g_xs1[NMAX * HDIM];
__device__ float g_ssu[NMAX], g_stu[NMAX], g_sss[NMAX], g_sts[NMAX];
__device__ float g_ssu2[NMAX], g_stu2[NMAX], g_sss2[NMAX], g_sts2[NMAX];

__device__ int g_s2s_us[EMAX];
__device__ int g_s2s_su[EMAX];
__device__ int g_rp_us [NMAX + 1];
__device__ int g_rp_su [NMAX + 1];
__device__ int g_cnt   [NMAX];
__device__ int g_cur   [NMAX];
__device__ int g_bsum  [1024];

__device__ int8_t g_wqh[120 * 1024];
__device__ int8_t g_wql[120 * 1024];
__device__ float  g_ws [1216];

// ------------------------------ helpers ------------------------------------
__device__ __forceinline__ uint32_t smem_u32(const void* p) {
    uint32_t a;
    asm("{ .reg .u64 t; cvta.to.shared.u64 t, %1; cvt.u32.u64 %0, t; }"
        : "=r"(a) : "l"(p));
    return a;
}
__device__ __forceinline__ void ldsm_x4(uint32_t* r, uint32_t addr) {
    asm volatile("ldmatrix.sync.aligned.m8n8.x4.shared.b16 {%0,%1,%2,%3}, [%4];"
                 : "=r"(r[0]), "=r"(r[1]), "=r"(r[2]), "=r"(r[3]) : "r"(addr));
}
__device__ __forceinline__ void mma_s8(int* c, const uint32_t* a,
                                       const uint32_t* b) {
    asm volatile("mma.sync.aligned.m16n8k32.row.col.s32.s8.s8.s32 "
                 "{%0,%1,%2,%3}, {%4,%5,%6,%7}, {%8,%9}, {%0,%1,%2,%3};"
                 : "+r"(c[0]), "+r"(c[1]), "+r"(c[2]), "+r"(c[3])
                 : "r"(a[0]), "r"(a[1]), "r"(a[2]), "r"(a[3]),
                   "r"(b[0]), "r"(b[1]));
}

// ---------------------------------------------------------------------------
// Dual GEMM (int8 2-limb): [Y1|Y2] = X[N,K] @ [W1|W2], fused scores.
// 512 thr, warp grid 2(m) x 8(n), tile 64 rows x 256 cols. B resident.
// ---------------------------------------------------------------------------
template<int K>
__global__ __launch_bounds__(512, 1)
void mma_dual_q(const float* __restrict__ A,
                const int8_t* __restrict__ Bqh, const int8_t* __restrict__ Bql,
                const float* __restrict__ wscale,
                const float* __restrict__ av1, const float* __restrict__ av2,
                float* __restrict__ Y1, float* __restrict__ Y2,
                float* __restrict__ s1, float* __restrict__ s2,
                int N, int nTiles)
{
    constexpr int TM = 64, MROWS = 256;
    constexpr int SAB = K + 16;          // byte stride
    constexpr int CH  = K / 8;           // 8-float chunks per row
    constexpr int IT  = TM * CH / 512;   // items/thread: 2 (K=128), 1 (K=64)
    constexpr int NT  = 4, NP = 2;
    constexpr int KS  = K / 32;
    constexpr int SM_AH = 4608;
    constexpr int SM_AL = SM_AH + TM * SAB;
    constexpr int SM_BH = SM_AL + TM * SAB;
    constexpr int SM_BL = SM_BH + MROWS * SAB;

    extern __shared__ char smem[];
    const uint32_t sb = smem_u32(smem);
    float* sbuf = (float*)smem;               // 512 floats (score partials)
    float* avsh = (float*)(smem + 2048);      // 256 (av1|av2)
    float* sbs  = (float*)(smem + 3072);      // 256 (w scales)
    float* sas  = (float*)(smem + 4096);      // 64  (row scales)

    const int tid  = threadIdx.x;
    const int wid  = tid >> 5;
    const int lane = tid & 31;
    const int wm   = wid & 1;
    const int wn   = wid >> 1;                // 0..7

    if (tid < 256) {
        avsh[tid] = (tid < 128) ? av1[tid] : av2[tid - 128];
        sbs[tid]  = wscale[tid];
    }

    // ---- B fill (both limbs, resident) ----
    for (int i = tid; i < MROWS * (K / 16); i += 512) {
        int r = i / (K / 16), c = i % (K / 16);
        size_t idx = (size_t)r * (K / 16) + c;
        *(uint4*)(smem + SM_BH + r * SAB + c * 16) = ((const uint4*)Bqh)[idx];
        *(uint4*)(smem + SM_BL + r * SAB + c * 16) = ((const uint4*)Bql)[idx];
    }

    int arow[2], brow[NP];
#pragma unroll
    for (int mt = 0; mt < 2; mt++)
        arow[mt] = (wm * 32 + mt * 16 + (lane & 15)) * SAB + ((lane >> 4) << 4);
#pragma unroll
    for (int np = 0; np < NP; np++)
        brow[np] = (wn * 32 + np * 16 + (lane & 7) + ((lane >> 4) << 3)) * SAB
                 + (((lane >> 3) & 1) << 4);

    float pf[IT][8];
    auto ldItem = [&](int rowBase, int j, float* f) {
        int i = tid + j * 512;
        int r = i / CH, c = i % CH;
        int gr = rowBase + r;
#pragma unroll
        for (int q = 0; q < 8; q++) f[q] = 0.f;
        if (gr < N) {
            size_t idx = (size_t)gr * (K / 4) + (size_t)c * 2;
            *(float4*)f       = ((const float4*)A)[idx];
            *(float4*)(f + 4) = ((const float4*)A)[idx + 1];
        }
    };
    auto stItem = [&](int j, const float* f) {
        int i = tid + j * 512;
        int r = i / CH, c = i % CH;
        float am = 0.f;
#pragma unroll
        for (int q = 0; q < 8; q++) am = fmaxf(am, fabsf(f[q]));
#pragma unroll
        for (int o = 1; o < CH; o <<= 1)
            am = fmaxf(am, __shfl_xor_sync(0xffffffffu, am, o));
        am = fmaxf(am, 1e-20f);
        float qs = 127.f / am;
        char hb[8], lb[8];
#pragma unroll
        for (int q = 0; q < 8; q++) {
            float t = f[q] * qs;
            int ih = __float2int_rn(t);
            int il = __float2int_rn((t - (float)ih) * 256.f);
            il = il > 127 ? 127 : (il < -127 ? -127 : il);
            hb[q] = (char)ih; lb[q] = (char)il;
        }
        int off = r * SAB + c * 8;
        *(uint2*)(smem + SM_AH + off) = *(uint2*)hb;
        *(uint2*)(smem + SM_AL + off) = *(uint2*)lb;
        if (c == 0) sas[r] = am * (1.f / 127.f);
    };

    if (blockIdx.x < nTiles)
#pragma unroll
        for (int j = 0; j < IT; j++) ldItem(blockIdx.x * TM, j, pf[j]);

    for (int tile = blockIdx.x; tile < nTiles; tile += gridDim.x) {
        const int rowBase = tile * TM;
        __syncthreads();
#pragma unroll
        for (int j = 0; j < IT; j++) stItem(j, pf[j]);
        __syncthreads();
        {
            int ntile = tile + gridDim.x;
            if (ntile < nTiles)
#pragma unroll
                for (int j = 0; j < IT; j++) ldItem(ntile * TM, j, pf[j]);
        }

        int acc1[2][NT][4], acc2[2][NT][4];
#pragma unroll
        for (int mt = 0; mt < 2; mt++)
#pragma unroll
            for (int nt = 0; nt < NT; nt++)
#pragma unroll
                for (int q = 0; q < 4; q++) { acc1[mt][nt][q] = 0; acc2[mt][nt][q] = 0; }

        // loop 1: acc1 += qh*ph ; acc2 += ql*ph
#pragma unroll
        for (int ks = 0; ks < KS; ks++) {
            uint32_t ah[2][4], al[2][4];
#pragma unroll
            for (int mt = 0; mt < 2; mt++) {
                ldsm_x4(ah[mt], sb + SM_AH + (uint32_t)(arow[mt] + ks * 32));
                ldsm_x4(al[mt], sb + SM_AL + (uint32_t)(arow[mt] + ks * 32));
            }
#pragma unroll
            for (int np = 0; np < NP; np++) {
                uint32_t t[4];
                ldsm_x4(t, sb + SM_BH + (uint32_t)(brow[np] + ks * 32));
#pragma unroll
                for (int mt = 0; mt < 2; mt++) {
                    mma_s8(acc1[mt][np * 2],     ah[mt], t);
                    mma_s8(acc1[mt][np * 2 + 1], ah[mt], t + 2);
                    mma_s8(acc2[mt][np * 2],     al[mt], t);
                    mma_s8(acc2[mt][np * 2 + 1], al[mt], t + 2);
                }
            }
        }
        // loop 2: acc2 += qh*pl
#pragma unroll
        for (int ks = 0; ks < KS; ks++) {
            uint32_t ah[2][4];
#pragma unroll
            for (int mt = 0; mt < 2; mt++)
                ldsm_x4(ah[mt], sb + SM_AH + (uint32_t)(arow[mt] + ks * 32));
#pragma unroll
            for (int np = 0; np < NP; np++) {
                uint32_t t[4];
                ldsm_x4(t, sb + SM_BL + (uint32_t)(brow[np] + ks * 32));
#pragma unroll
                for (int mt = 0; mt < 2; mt++) {
                    mma_s8(acc2[mt][np * 2],     ah[mt], t);
                    mma_s8(acc2[mt][np * 2 + 1], ah[mt], t + 2);
                }
            }
        }

        // epilogue: dequant, store, fused scores
        const int half = wn >> 2;
        const int cb   = (wn & 3) * 32;
        float* Yo = half ? Y2 : Y1;
#pragma unroll
        for (int mt = 0; mt < 2; mt++) {
            int r0 = wm * 32 + mt * 16 + (lane >> 2);
            int gr0 = rowBase + r0, gr1 = gr0 + 8;
            float fa0 = sas[r0] * (1.f / 256.f);
            float fa1 = sas[r0 + 8] * (1.f / 256.f);
            float p0 = 0.f, p1 = 0.f;
#pragma unroll
            for (int nt = 0; nt < NT; nt++) {
                int lc = cb + nt * 8 + (lane & 3) * 2;
                int cg = half * 128 + lc;
                float b0 = sbs[cg], b1 = sbs[cg + 1];
                float v0 = (float)(acc1[mt][nt][0] * 256 + acc2[mt][nt][0]) * fa0 * b0;
                float v1 = (float)(acc1[mt][nt][1] * 256 + acc2[mt][nt][1]) * fa0 * b1;
                float v2 = (float)(acc1[mt][nt][2] * 256 + acc2[mt][nt][2]) * fa1 * b0;
                float v3 = (float)(acc1[mt][nt][3] * 256 + acc2[mt][nt][3]) * fa1 * b1;
                if (gr0 < N) *(float2*)(Yo + (size_t)gr0 * HDIM + lc) = make_float2(v0, v1);
                if (gr1 < N) *(float2*)(Yo + (size_t)gr1 * HDIM + lc) = make_float2(v2, v3);
                float a0 = avsh[half * 128 + lc], a1 = avsh[half * 128 + lc + 1];
                p0 = fmaf(v0, a0, fmaf(v1, a1, p0));
                p1 = fmaf(v2, a0, fmaf(v3, a1, p1));
            }
            p0 += __shfl_xor_sync(0xffffffffu, p0, 1);
            p0 += __shfl_xor_sync(0xffffffffu, p0, 2);
            p1 += __shfl_xor_sync(0xffffffffu, p1, 1);
            p1 += __shfl_xor_sync(0xffffffffu, p1, 2);
            if ((lane & 3) == 0) {
                sbuf[half * 256 + (wn & 3) * 64 + r0]     = p0;
                sbuf[half * 256 + (wn & 3) * 64 + r0 + 8] = p1;
            }
        }
        __syncthreads();
        for (int i = tid; i < 128; i += 512) {
            int row = i & 63, h = i >> 6;
            int gr = rowBase + row;
            if (gr < N)
                (h ? s2 : s1)[gr] = sbuf[h * 256 + row] + sbuf[h * 256 + 64 + row]
                                  + sbuf[h * 256 + 128 + row] + sbuf[h * 256 + 192 + row];
        }
    }
}

// ---------------------------------------------------------------------------
// Final GEMM (int8 2-limb): Y[N,64] = X[N,128] @ W + bias.
// 512 thr, warp grid 4(m) x 4(n), tile 128 rows x 64 cols.
// ---------------------------------------------------------------------------
__global__ __launch_bounds__(512, 1)
void mma_final_q(const float* __restrict__ A,
                 const int8_t* __restrict__ Bqh, const int8_t* __restrict__ Bql,
                 const float* __restrict__ wscale, const float* __restrict__ bias,
                 float* __restrict__ Y, int N, int nTiles)
{
    constexpr int K = 128, TM = 128, MROWS = 64;
    constexpr int SAB = K + 16;
    constexpr int CH  = K / 8;            // 16
    constexpr int IT  = TM * CH / 512;    // 4
    constexpr int NT  = 2, NP = 1;
    constexpr int KS  = K / 32;           // 4
    constexpr int SM_AH = 4608;
    constexpr int SM_AL = SM_AH + TM * SAB;
    constexpr int SM_BH = SM_AL + TM * SAB;
    constexpr int SM_BL = SM_BH + MROWS * SAB;

    extern __shared__ char smem[];
    const uint32_t sb = smem_u32(smem);
    float* bsh = (float*)(smem + 2048);   // 64 bias
    float* sbs = (float*)(smem + 3072);   // 64 scales
    float* sas = (float*)(smem + 4096);   // 128 row scales

    const int tid  = threadIdx.x;
    const int wid  = tid >> 5;
    const int lane = tid & 31;
    const int wm   = wid & 3;
    const int wn   = wid >> 2;

    if (tid < 64) { bsh[tid] = bias[tid]; sbs[tid] = wscale[tid]; }

    for (int i = tid; i < MROWS * (K / 16); i += 512) {
        int r = i / (K / 16), c = i % (K / 16);
        size_t idx = (size_t)r * (K / 16) + c;
        *(uint4*)(smem + SM_BH + r * SAB + c * 16) = ((const uint4*)Bqh)[idx];
        *(uint4*)(smem + SM_BL + r * SAB + c * 16) = ((const uint4*)Bql)[idx];
    }

    int arow[2], brow[NP];
#pragma unroll
    for (int mt = 0; mt < 2; mt++)
        arow[mt] = (wm * 32 + mt * 16 + (lane & 15)) * SAB + ((lane >> 4) << 4);
#pragma unroll
    for (int np = 0; np < NP; np++)
        brow[np] = (wn * 16 + np * 16 + (lane & 7) + ((lane >> 4) << 3)) * SAB
                 + (((lane >> 3) & 1) << 4);

    float pf[IT][8];
    auto ldItem = [&](int rowBase, int j, float* f) {
        int i = tid + j * 512;
        int r = i / CH, c = i % CH;
        int gr = rowBase + r;
#pragma unroll
        for (int q = 0; q < 8; q++) f[q] = 0.f;
        if (gr < N) {
            size_t idx = (size_t)gr * (K / 4) + (size_t)c * 2;
            *(float4*)f       = ((const float4*)A)[idx];
            *(float4*)(f + 4) = ((const float4*)A)[idx + 1];
        }
    };
    auto stItem = [&](int j, const float* f) {
        int i = tid + j * 512;
        int r = i / CH, c = i % CH;
        float am = 0.f;
#pragma unroll
        for (int q = 0; q < 8; q++) am = fmaxf(am, fabsf(f[q]));
#pragma unroll
        for (int o = 1; o < CH; o <<= 1)
            am = fmaxf(am, __shfl_xor_sync(0xffffffffu, am, o));
        am = fmaxf(am, 1e-20f);
        float qs = 127.f / am;
        char hb[8], lb[8];
#pragma unroll
        for (int q = 0; q < 8; q++) {
            float t = f[q] * qs;
            int ih = __float2int_rn(t);
            int il = __float2int_rn((t - (float)ih) * 256.f);
            il = il > 127 ? 127 : (il < -127 ? -127 : il);
            hb[q] = (char)ih; lb[q] = (char)il;
        }
        int off = r * SAB + c * 8;
        *(uint2*)(smem + SM_AH + off) = *(uint2*)hb;
        *(uint2*)(smem + SM_AL + off) = *(uint2*)lb;
        if (c == 0) sas[r] = am * (1.f / 127.f);
    };

    if (blockIdx.x < nTiles)
#pragma unroll
        for (int j = 0; j < IT; j++) ldItem(blockIdx.x * TM, j, pf[j]);

    for (int tile = blockIdx.x; tile < nTiles; tile += gridDim.x) {
        const int rowBase = tile * TM;
        __syncthreads();
#pragma unroll
        for (int j = 0; j < IT; j++) stItem(j, pf[j]);
        __syncthreads();
        {
            int ntile = tile + gridDim.x;
            if (ntile < nTiles)
#pragma unroll
                for (int j = 0; j < IT; j++) ldItem(ntile * TM, j, pf[j]);
        }

        int acc1[2][NT][4], acc2[2][NT][4];
#pragma unroll
        for (int mt = 0; mt < 2; mt++)
#pragma unroll
            for (int nt = 0; nt < NT; nt++)
#pragma unroll
                for (int q = 0; q < 4; q++) { acc1[mt][nt][q] = 0; acc2[mt][nt][q] = 0; }

#pragma unroll
        for (int ks = 0; ks < KS; ks++) {
            uint32_t ah[2][4], al[2][4];
#pragma unroll
            for (int mt = 0; mt < 2; mt++) {
                ldsm_x4(ah[mt], sb + SM_AH + (uint32_t)(arow[mt] + ks * 32));
                ldsm_x4(al[mt], sb + SM_AL + (uint32_t)(arow[mt] + ks * 32));
            }
#pragma unroll
            for (int np = 0; np < NP; np++) {
                uint32_t t[4];
                ldsm_x4(t, sb + SM_BH + (uint32_t)(brow[np] + ks * 32));
#pragma unroll
                for (int mt = 0; mt < 2; mt++) {
                    mma_s8(acc1[mt][np * 2],     ah[mt], t);
                    mma_s8(acc1[mt][np * 2 + 1], ah[mt], t + 2);
                    mma_s8(acc2[mt][np * 2],     al[mt], t);
                    mma_s8(acc2[mt][np * 2 + 1], al[mt], t + 2);
                }
            }
        }
#pragma unroll
        for (int ks = 0; ks < KS; ks++) {
            uint32_t ah[2][4];
#pragma unroll
            for (int mt = 0; mt < 2; mt++)
                ldsm_x4(ah[mt], sb + SM_AH + (uint32_t)(arow[mt] + ks * 32));
#pragma unroll
            for (int np = 0; np < NP; np++) {
                uint32_t t[4];
                ldsm_x4(t, sb + SM_BL + (uint32_t)(brow[np] + ks * 32));
#pragma unroll
                for (int mt = 0; mt < 2; mt++) {
                    mma_s8(acc2[mt][np * 2],     ah[mt], t);
                    mma_s8(acc2[mt][np * 2 + 1], ah[mt], t + 2);
                }
            }
        }

#pragma unroll
        for (int mt = 0; mt < 2; mt++) {
            int r0 = wm * 32 + mt * 16 + (lane >> 2);
            int gr0 = rowBase + r0, gr1 = gr0 + 8;
            float fa0 = sas[r0] * (1.f / 256.f);
            float fa1 = sas[r0 + 8] * (1.f / 256.f);
#pragma unroll
            for (int nt = 0; nt < NT; nt++) {
                int cc = wn * 16 + nt * 8 + (lane & 3) * 2;
                float b0 = sbs[cc], b1 = sbs[cc + 1];
                float v0 = (float)(acc1[mt][nt][0] * 256 + acc2[mt][nt][0]) * fa0 * b0 + bsh[cc];
                float v1 = (float)(acc1[mt][nt][1] * 256 + acc2[mt][nt][1]) * fa0 * b1 + bsh[cc + 1];
                float v2 = (float)(acc1[mt][nt][2] * 256 + acc2[mt][nt][2]) * fa1 * b0 + bsh[cc];
                float v3 = (float)(acc1[mt][nt][3] * 256 + acc2[mt][nt][3]) * fa1 * b1 + bsh[cc + 1];
                if (gr0 < N) *(float2*)(Y + (size_t)gr0 * MROWS + cc) = make_float2(v0, v1);
                if (gr1 < N) *(float2*)(Y + (size_t)gr1 * MROWS + cc) = make_float2(v2, v3);
            }
        }
    }
}

// ---------------------------------------------------------------------------
// weight quantize: warp per output row of Wt (= column of W)
// ---------------------------------------------------------------------------
struct WQ { const float* w[10]; int K[10]; int M[10]; int qoff[10]; int soff[10]; };

__global__ void wquant_all(WQ wb, int8_t* __restrict__ qh, int8_t* __restrict__ ql,
                           float* __restrict__ ws)
{
    int warp = (blockIdx.x * blockDim.x + threadIdx.x) >> 5;
    int lane = threadIdx.x & 31;
    int row = warp, m = 0;
    for (; m < 10; m++) { if (row < wb.M[m]) break; row -= wb.M[m]; }
    if (m >= 10) return;
    int K = wb.K[m], M = wb.M[m];
    const float* W = wb.w[m];
    float vals[4];
    float vmax = 0.f;
    int nt = K / 32;
    for (int t = 0; t < nt; t++) {
        int k = lane + 32 * t;
        float v = W[(size_t)k * M + row];
        vals[t] = v;
        vmax = fmaxf(vmax, fabsf(v));
    }
#pragma unroll
    for (int o = 16; o; o >>= 1) vmax = fmaxf(vmax, __shfl_xor_sync(0xffffffffu, vmax, o));
    vmax = fmaxf(vmax, 1e-20f);
    float qs = 127.f / vmax;
    for (int t = 0; t < nt; t++) {
        int k = lane + 32 * t;
        float x = vals[t] * qs;
        int ih = __float2int_rn(x);
        int il = __float2int_rn((x - (float)ih) * 256.f);
        il = il > 127 ? 127 : (il < -127 ? -127 : il);
        size_t off = (size_t)wb.qoff[m] + (size_t)row * K + k;
        qh[off] = (int8_t)ih;
        ql[off] = (int8_t)il;
    }
    if (lane == 0) ws[wb.soff[m] + row] = vmax * (1.f / 127.f);
}

// ---------------------------------------------------------------------------
// CSR build kernels (validated r4-r9)
// ---------------------------------------------------------------------------
__global__ void hist_kernel(const int* __restrict__ ti, int* __restrict__ cnt, int E)
{
    int e = blockIdx.x * blockDim.x + threadIdx.x;
    if (e < E) atomicAdd(cnt + __ldg(ti + e), 1);
}

__global__ void scan_partial(const int* __restrict__ cnt, int* __restrict__ bsum, int N)
{
    __shared__ int ws[8];
    int i = blockIdx.x * 256 + threadIdx.x;
    int v = (i < N) ? cnt[i] : 0;
#pragma unroll
    for (int o = 16; o; o >>= 1) v += __shfl_xor_sync(0xffffffffu, v, o);
    int lane = threadIdx.x & 31, wid = threadIdx.x >> 5;
    if (lane == 0) ws[wid] = v;
    __syncthreads();
    if (threadIdx.x == 0) {
        int t = 0;
#pragma unroll
        for (int j = 0; j < 8; j++) t += ws[j];
        bsum[blockIdx.x] = t;
    }
}

__global__ void scan_block_par(int* __restrict__ bsum, int nb)
{
    __shared__ int ws[16];
    int tid = threadIdx.x, lane = tid & 31, w = tid >> 5;
    int v = (tid < nb) ? bsum[tid] : 0;
    int x = v;
#pragma unroll
    for (int o = 1; o < 32; o <<= 1) {
        int y = __shfl_up_sync(0xffffffffu, x, o);
        if (lane >= o) x += y;
    }
    if (lane == 31) ws[w] = x;
    __syncthreads();
    if (w == 0 && lane < 16) {
        int q = ws[lane], sx = q;
#pragma unroll
        for (int o = 1; o < 16; o <<= 1) {
            int y = __shfl_up_sync(0x0000ffffu, sx, o);
            if (lane >= o) sx += y;
        }
        ws[lane] = sx - q;
    }
    __syncthreads();
    if (tid < nb) bsum[tid] = (x - v) + ws[w];
}

__global__ void scan_final(const int* __restrict__ cnt, const int* __restrict__ bsum,
                           int* __restrict__ rowptr, int* __restrict__ cur, int N, int E)
{
    __shared__ int ws[8];
    int i = blockIdx.x * 256 + threadIdx.x;
    int lane = threadIdx.x & 31, wid = threadIdx.x >> 5;
    int v = (i < N) ? cnt[i] : 0;
    int x = v;
#pragma unroll
    for (int o = 1; o < 32; o <<= 1) {
        int y = __shfl_up_sync(0xffffffffu, x, o);
        if (lane >= o) x += y;
    }
    if (lane == 31) ws[wid] = x;
    __syncthreads();
    if (wid == 0) {
        int w = (lane < 8) ? ws[lane] : 0;
        int sx = w;
#pragma unroll
        for (int o = 1; o < 8; o <<= 1) {
            int y = __shfl_up_sync(0xffffffffu, sx, o);
            if (lane >= o) sx += y;
        }
        if (lane < 8) ws[lane] = sx - w;
    }
    __syncthreads();
    int excl = (x - v) + ws[wid] + bsum[blockIdx.x];
    if (i < N) { rowptr[i] = excl; cur[i] = excl; }
    if (i == N - 1) rowptr[N] = excl + v;
}

__global__ void scatter_kernel(const int* __restrict__ si, const int* __restrict__ ti,
                               int* __restrict__ cur, int* __restrict__ s2s, int E)
{
    int e = blockIdx.x * blockDim.x + threadIdx.x;
    if (e >= E) return;
    int s1 = __ldg(si + e);
    int s2 = __ldg(si + s1);           // faithful src[si][si]
    int t  = __ldg(ti + e);
    int pos = atomicAdd(cur + t, 1);
    s2s[pos] = s2;
}

// ---------------------------------------------------------------------------
// fused aggregation + finalize: warp per target (validated r4-r9)
// ---------------------------------------------------------------------------
__global__ void agg_kernel(const int* __restrict__ rowptr, const int* __restrict__ s2s,
                           const float* __restrict__ src, const float* __restrict__ tgt,
                           const float* __restrict__ ssrc, const float* __restrict__ stgt,
                           float* __restrict__ out, int Ntgt)
{
    int t    = (blockIdx.x * blockDim.x + threadIdx.x) >> 5;
    int lane = threadIdx.x & 31;
    if (t >= Ntgt) return;

    int start = __ldg(rowptr + t), end = __ldg(rowptr + t + 1);
    float stt = __ldg(stgt + t);

    float4 acc = make_float4(0.f, 0.f, 0.f, 0.f);
    float dsum = 0.f;

    for (int base = start; base < end; base += 32) {
        int n = min(32, end - base);
        int sid = 0; float att = 0.f;
        if (lane < n) {
            sid = __ldg(s2s + base + lane);
            float logit = __ldg(ssrc + sid) + stt;
            float lr = logit > 0.f ? logit : LEAK * logit;
            att = expf(lr);
            dsum += att;
        }
        int j = 0;
        for (; j + 4 <= n; j += 4) {
            int   s0 = __shfl_sync(0xffffffffu, sid, j);
            int   s1 = __shfl_sync(0xffffffffu, sid, j + 1);
            int   s2 = __shfl_sync(0xffffffffu, sid, j + 2);
            int   s3 = __shfl_sync(0xffffffffu, sid, j + 3);
            float a0 = __shfl_sync(0xffffffffu, att, j);
            float a1 = __shfl_sync(0xffffffffu, att, j + 1);
            float a2 = __shfl_sync(0xffffffffu, att, j + 2);
            float a3 = __shfl_sync(0xffffffffu, att, j + 3);
            float4 v0 = __ldg((const float4*)src + (size_t)s0 * 32 + lane);
            float4 v1 = __ldg((const float4*)src + (size_t)s1 * 32 + lane);
            float4 v2 = __ldg((const float4*)src + (size_t)s2 * 32 + lane);
            float4 v3 = __ldg((const float4*)src + (size_t)s3 * 32 + lane);
            acc.x = fmaf(a0, v0.x, fmaf(a1, v1.x, fmaf(a2, v2.x, fmaf(a3, v3.x, acc.x))));
            acc.y = fmaf(a0, v0.y, fmaf(a1, v1.y, fmaf(a2, v2.y, fmaf(a3, v3.y, acc.y))));
            acc.z = fmaf(a0, v0.z, fmaf(a1, v1.z, fmaf(a2, v2.z, fmaf(a3, v3.z, acc.z))));
            acc.w = fmaf(a0, v0.w, fmaf(a1, v1.w, fmaf(a2, v2.w, fmaf(a3, v3.w, acc.w))));
        }
        for (; j < n; j++) {
            int   sj = __shfl_sync(0xffffffffu, sid, j);
            float aj = __shfl_sync(0xffffffffu, att, j);
            float4 v = __ldg((const float4*)src + (size_t)sj * 32 + lane);
            acc.x = fmaf(aj, v.x, acc.x);
            acc.y = fmaf(aj, v.y, acc.y);
            acc.z = fmaf(aj, v.z, acc.z);
            acc.w = fmaf(aj, v.w, acc.w);
        }
    }
#pragma unroll
    for (int o = 16; o; o >>= 1) dsum += __shfl_xor_sync(0xffffffffu, dsum, o);

    float inv = 1.f / (dsum + EPS_C);
    float4 tg = __ldg((const float4*)tgt + (size_t)t * 32 + lane);
    float4 o;
    o.x = fmaxf(fmaf(acc.x, inv, tg.x), 0.f);
    o.y = fmaxf(fmaf(acc.y, inv, tg.y), 0.f);
    o.z = fmaxf(fmaf(acc.z, inv, tg.z), 0.f);
    o.w = fmaxf(fmaf(acc.w, inv, tg.w), 0.f);
    ((float4*)out)[(size_t)t * 32 + lane] = o;
}

// ---------------------------------------------------------------------------
// host driver
// ---------------------------------------------------------------------------
template<int K>
static void launch_dual(const float* A, const int8_t* Bqh, const int8_t* Bql,
                        const float* wscale, const float* av1, const float* av2,
                        float* Y1, float* Y2, float* s1, float* s2, int N,
                        cudaStream_t st)
{
    constexpr size_t smemsz = 4608 + 2 * (size_t)(64 * (K + 16))
                                   + 2 * (size_t)(256 * (K + 16));
    cudaFuncSetAttribute(mma_dual_q<K>,
                         cudaFuncAttributeMaxDynamicSharedMemorySize, (int)smemsz);
    int tiles = (N + 63) / 64;
    int grid  = tiles < 148 ? tiles : 148;
    mma_dual_q<K><<<grid, 512, smemsz, st>>>(A, Bqh, Bql, wscale, av1, av2,
                                             Y1, Y2, s1, s2, N, tiles);
}

static void launch_final(const float* A, const int8_t* Bqh, const int8_t* Bql,
                         const float* wscale, const float* bias, float* Y, int N,
                         cudaStream_t st)
{
    constexpr size_t smemsz = 4608 + 2 * (size_t)(128 * 144) + 2 * (size_t)(64 * 144);
    cudaFuncSetAttribute(mma_final_q,
                         cudaFuncAttributeMaxDynamicSharedMemorySize, (int)smemsz);
    int tiles = (N + 127) / 128;
    int grid  = tiles < 148 ? tiles : 148;
    mma_final_q<<<grid, 512, smemsz, st>>>(A, Bqh, Bql, wscale, bias, Y, N, tiles);
}

static void build_csr(const int* si, const int* ti, int E, int Ntgt,
                      int* cnt, int* cur, int* bsum, int* rowptr, int* s2s,
                      cudaStream_t st)
{
    cudaMemsetAsync(cnt, 0, (size_t)Ntgt * sizeof(int), st);
    hist_kernel<<<(E + 255) / 256, 256, 0, st>>>(ti, cnt, E);
    int nb = (Ntgt + 255) / 256;
    scan_partial<<<nb, 256, 0, st>>>(cnt, bsum, Ntgt);
    scan_block_par<<<1, 512, 0, st>>>(bsum, nb);
    scan_final<<<nb, 256, 0, st>>>(cnt, bsum, rowptr, cur, Ntgt, E);
    scatter_kernel<<<(E + 255) / 256, 256, 0, st>>>(si, ti, cur, s2s, E);
}

extern "C" void kernel_launch(void* const* d_in, const int* in_sizes, int n_in,
                              void* d_out, int out_size)
{
    const float* x_user = (const float*)d_in[0];
    const float* x_spot = (const float*)d_in[1];
    const int*   e_us   = (const int*)d_in[2];
    const int*   e_su   = (const int*)d_in[3];
    const float* a_us0 = (const float*)d_in[6];
    const float* a_su0 = (const float*)d_in[9];
    const float* a_us1 = (const float*)d_in[12];
    const float* a_su1 = (const float*)d_in[15];
    const float* b_ou  = (const float*)d_in[17];
    const float* b_os  = (const float*)d_in[19];

    const int N_USER = in_sizes[0] / 64;
    const int N_SPOT = in_sizes[1] / 64;
    const int E      = in_sizes[2] / 2;

    const int* si_us = e_us;
    const int* ti_us = e_us + E;
    const int* si_su = e_su;
    const int* ti_su = e_su + E;

    float *pA, *pB, *pC, *pD, *pA2, *pB2, *pC2, *pD2, *p_xu1, *p_xs1;
    float *p_ssu, *p_stu, *p_sss, *p_sts, *p_ssu2, *p_stu2, *p_sss2, *p_sts2;
    int *p_s2us, *p_s2su, *p_rpus, *p_rpsu, *p_cnt, *p_cur, *p_bsum;
    int8_t *p_wqh, *p_wql;
    float *p_ws;
    cudaGetSymbolAddress((void**)&pA, g_A);
    cudaGetSymbolAddress((void**)&pB, g_B);
    cudaGetSymbolAddress((void**)&pC, g_C);
    cudaGetSymbolAddress((void**)&pD, g_D);
    cudaGetSymbolAddress((void**)&pA2, g_A2);
    cudaGetSymbolAddress((void**)&pB2, g_B2);
    cudaGetSymbolAddress((void**)&pC2, g_C2);
    cudaGetSymbolAddress((void**)&pD2, g_D2);
    cudaGetSymbolAddress((void**)&p_xu1, g_xu1);
    cudaGetSymbolAddress((void**)&p_xs1, g_xs1);
    cudaGetSymbolAddress((void**)&p_ssu, g_ssu);
    cudaGetSymbolAddress((void**)&p_stu, g_stu);
    cudaGetSymbolAddress((void**)&p_sss, g_sss);
    cudaGetSymbolAddress((void**)&p_sts, g_sts);
    cudaGetSymbolAddress((void**)&p_ssu2, g_ssu2);
    cudaGetSymbolAddress((void**)&p_stu2, g_stu2);
    cudaGetSymbolAddress((void**)&p_sss2, g_sss2);
    cudaGetSymbolAddress((void**)&p_sts2, g_sts2);
    cudaGetSymbolAddress((void**)&p_s2us, g_s2s_us);
    cudaGetSymbolAddress((void**)&p_s2su, g_s2s_su);
    cudaGetSymbolAddress((void**)&p_rpus, g_rp_us);
    cudaGetSymbolAddress((void**)&p_rpsu, g_rp_su);
    cudaGetSymbolAddress((void**)&p_cnt, g_cnt);
    cudaGetSymbolAddress((void**)&p_cur, g_cur);
    cudaGetSymbolAddress((void**)&p_bsum, g_bsum);
    cudaGetSymbolAddress((void**)&p_wqh, g_wqh);
    cudaGetSymbolAddress((void**)&p_wql, g_wql);
    cudaGetSymbolAddress((void**)&p_ws, g_ws);

    float* out_xu = (float*)d_out;
    float* out_xs = out_xu + (size_t)N_USER * HDIM;
    float* out_ou = out_xs + (size_t)N_SPOT * HDIM;
    float* out_os = out_ou + (size_t)N_USER * 64;

    // fork stream + events
    cudaStream_t sf;
    cudaStreamCreateWithFlags(&sf, cudaStreamNonBlocking);
    cudaEvent_t eStart, eU, eB, eSu, eGu, eGs, eA2, eEnd;
    cudaEventCreateWithFlags(&eStart, cudaEventDisableTiming);
    cudaEventCreateWithFlags(&eU, cudaEventDisableTiming);
    cudaEventCreateWithFlags(&eB, cudaEventDisableTiming);
    cudaEventCreateWithFlags(&eSu, cudaEventDisableTiming);
    cudaEventCreateWithFlags(&eGu, cudaEventDisableTiming);
    cudaEventCreateWithFlags(&eGs, cudaEventDisableTiming);
    cudaEventCreateWithFlags(&eA2, cudaEventDisableTiming);
    cudaEventCreateWithFlags(&eEnd, cudaEventDisableTiming);

    // ---- fork ----
    cudaEventRecord(eStart, 0);
    cudaStreamWaitEvent(sf, eStart, 0);

    // side: CSR builds (under the L0 GEMMs)
    build_csr(si_us, ti_us, E, N_SPOT, p_cnt, p_cur, p_bsum, p_rpus, p_s2us, sf);
    cudaEventRecord(eU, sf);
    build_csr(si_su, ti_su, E, N_USER, p_cnt, p_cur, p_bsum, p_rpsu, p_s2su, sf);

    // main: weight quantization + layer-0 GEMMs
    {
        WQ wb;
        const float* src[10] = {
            (const float*)d_in[4],  (const float*)d_in[8],
            (const float*)d_in[5],  (const float*)d_in[7],
            (const float*)d_in[10], (const float*)d_in[14],
            (const float*)d_in[11], (const float*)d_in[13],
            (const float*)d_in[16], (const float*)d_in[18]
        };
        const int Ks[10] = {64, 64, 64, 64, 128, 128, 128, 128, 128, 128};
        const int Ms[10] = {128, 128, 128, 128, 128, 128, 128, 128, 64, 64};
        const int Qs[10] = {0, 8192, 16384, 24576, 32768, 49152,
                            65536, 81920, 98304, 106496};
        const int Ss[10] = {0, 128, 256, 384, 512, 640, 768, 896, 1024, 1088};
        for (int i = 0; i < 10; i++) {
            wb.w[i] = src[i]; wb.K[i] = Ks[i]; wb.M[i] = Ms[i];
            wb.qoff[i] = Qs[i]; wb.soff[i] = Ss[i];
        }
        wquant_all<<<(1152 * 32 + 255) / 256, 256>>>(wb, p_wqh, p_wql, p_ws);
    }
    launch_dual<64>(x_user, p_wqh + 0, p_wql + 0, p_ws + 0, a_us0, a_su0 + HDIM,
                    pA, pD, p_ssu, p_sts, N_USER, 0);
    launch_dual<64>(x_spot, p_wqh + 16384, p_wql + 16384, p_ws + 256,
                    a_us0 + HDIM, a_su0, pB, pC, p_stu, p_sss, N_SPOT, 0);
    cudaEventRecord(eB, 0);

    const int AGG_T = 256;
    auto aggGrid = [&](int n) { return (n * 32 + AGG_T - 1) / AGG_T; };

    // side: agg_su alone -> G128(xu1)
    cudaStreamWaitEvent(sf, eB, 0);
    agg_kernel<<<aggGrid(N_USER), AGG_T, 0, sf>>>(p_rpsu, p_s2su, pC, pD,
                                                  p_sss, p_sts, p_xu1, N_USER);
    cudaEventRecord(eSu, sf);
    launch_dual<128>(p_xu1, p_wqh + 32768, p_wql + 32768, p_ws + 512,
                     a_us1, a_su1 + HDIM, pA2, pD2, p_ssu2, p_sts2, N_USER, sf);
    cudaEventRecord(eGu, sf);

    // main: agg_us staggered; then G128(xs1)
    cudaStreamWaitEvent(0, eU, 0);
    cudaStreamWaitEvent(0, eSu, 0);
    agg_kernel<<<aggGrid(N_SPOT), AGG_T>>>(p_rpus, p_s2us, pA, pB,
                                           p_ssu, p_stu, p_xs1, N_SPOT);
    launch_dual<128>(p_xs1, p_wqh + 65536, p_wql + 65536, p_ws + 768,
                     a_us1 + HDIM, a_su1, pB2, pC2, p_stu2, p_sss2, N_SPOT, 0);
    cudaEventRecord(eGs, 0);

    // main: agg_us2 -> final_s
    cudaStreamWaitEvent(0, eGu, 0);
    agg_kernel<<<aggGrid(N_SPOT), AGG_T>>>(p_rpus, p_s2us, pA2, pB2,
                                           p_ssu2, p_stu2, out_xs, N_SPOT);
    cudaEventRecord(eA2, 0);
    launch_final(out_xs, p_wqh + 106496, p_wql + 106496, p_ws + 1088,
                 b_os, out_os, N_SPOT, 0);

    // side: agg_su2 -> final_u
    cudaStreamWaitEvent(sf, eGs, 0);
    cudaStreamWaitEvent(sf, eA2, 0);
    agg_kernel<<<aggGrid(N_USER), AGG_T, 0, sf>>>(p_rpsu, p_s2su, pC2, pD2,
                                                  p_sss2, p_sts2, out_xu, N_USER);
    launch_final(out_xu, p_wqh + 98304, p_wql + 98304, p_ws + 1024,
                 b_ou, out_ou, N_USER, sf);
    cudaEventRecord(eEnd, sf);

    // ---- join ----
    cudaStreamWaitEvent(0, eEnd, 0);
}

// round 11
// speedup vs baseline: 1.6708x; 1.6708x over previous
#include <cuda_runtime.h>
#include <cuda_bf16.h>
#include <cstdint>

// ---------------------------------------------------------------------------
// HeteroSAGEAttention on GB300 — round 11: revert to r9 (best validated,
// 539.7us) + merged GEMM mainloop (A-frags loaded once per k-step, both B
// limbs streamed against them: 14 -> 12 ldsm per k-step, same mma count).
// int8 IMMA experiment reverted (no MAC-rate advantage on sm_103 legacy path).
// ---------------------------------------------------------------------------

#define NMAX   100000
#define EMAX   500000
#define HDIM   128
#define LEAK   0.2f
#define EPS_C  1e-6f

// ------------------------- scratch (__device__ globals) --------------------
__device__ float g_A  [NMAX * HDIM];
__device__ float g_B  [NMAX * HDIM];
__device__ float g_C  [NMAX * HDIM];
__device__ float g_D  [NMAX * HDIM];
__device__ float g_A2 [NMAX * HDIM];
__device__ float g_B2 [NMAX * HDIM];
__device__ float g_C2 [NMAX * HDIM];
__device__ float g_D2 [NMAX * HDIM];
__device__ float g_xu1[NMAX * HDIM];
__device__ float g_xs1[NMAX * HDIM];
__device__ float g_ssu[NMAX], g_stu[NMAX], g_sss[NMAX], g_sts[NMAX];
__device__ float g_ssu2[NMAX], g_stu2[NMAX], g_sss2[NMAX], g_sts2[NMAX];

__device__ int g_s2s_us[EMAX];
__device__ int g_s2s_su[EMAX];
__device__ int g_rp_us [NMAX + 1];
__device__ int g_rp_su [NMAX + 1];
__device__ int g_cnt   [NMAX];
__device__ int g_cur   [NMAX];
__device__ int g_bsum  [1024];

__device__ __nv_bfloat16 g_wh[120 * 1024];
__device__ __nv_bfloat16 g_wl[120 * 1024];

// ------------------------------ helpers ------------------------------------
__device__ __forceinline__ uint32_t smem_u32(const void* p) {
    uint32_t a;
    asm("{ .reg .u64 t; cvta.to.shared.u64 t, %1; cvt.u32.u64 %0, t; }"
        : "=r"(a) : "l"(p));
    return a;
}
__device__ __forceinline__ void ldsm_x4(uint32_t* r, uint32_t addr) {
    asm volatile("ldmatrix.sync.aligned.m8n8.x4.shared.b16 {%0,%1,%2,%3}, [%4];"
                 : "=r"(r[0]), "=r"(r[1]), "=r"(r[2]), "=r"(r[3]) : "r"(addr));
}
__device__ __forceinline__ void mma_bf16(float* c, const uint32_t* a,
                                         const uint32_t* b) {
    asm volatile("mma.sync.aligned.m16n8k16.row.col.f32.bf16.bf16.f32 "
                 "{%0,%1,%2,%3}, {%4,%5,%6,%7}, {%8,%9}, {%0,%1,%2,%3};"
                 : "+f"(c[0]), "+f"(c[1]), "+f"(c[2]), "+f"(c[3])
                 : "r"(a[0]), "r"(a[1]), "r"(a[2]), "r"(a[3]),
                   "r"(b[0]), "r"(b[1]));
}
__device__ __forceinline__ void split8(const float* f, uint4& vh, uint4& vl) {
    __nv_bfloat16 h[8], l[8];
#pragma unroll
    for (int j = 0; j < 8; j++) {
        h[j] = __float2bfloat16(f[j]);
        l[j] = __float2bfloat16(f[j] - __bfloat162float(h[j]));
    }
    vh = *(const uint4*)h;
    vl = *(const uint4*)l;
}

// ---------------------------------------------------------------------------
// Persistent GEMM core with A register-prefetch pipeline and merged mainloop.
// Y = X[N,K] @ W (W pre-transposed [MROWS][K] bf16 hi/lo). B resident.
// 512 threads, warp grid 4(m) x 4(n).
// Per k-step: load ahi/alo once; stream Bhi (x ahi, x alo) and Blo (x ahi).
// DUAL: MROWS=256, outputs [Y1|Y2] + fused scores s1,s2. else single + bias.
// ---------------------------------------------------------------------------
template<int K, int MROWS, bool DUAL, bool BIAS>
__global__ __launch_bounds__(512, 1)
void mma_core(const float* __restrict__ A,
              const __nv_bfloat16* __restrict__ Bhi, const __nv_bfloat16* __restrict__ Blo,
              const float* __restrict__ av1, const float* __restrict__ av2,
              const float* __restrict__ bias,
              float* __restrict__ Y1, float* __restrict__ Y2,
              float* __restrict__ s1, float* __restrict__ s2,
              int N, int nTiles)
{
    constexpr int SA = K + 8;
    constexpr int WN = MROWS / 4;
    constexpr int NT = WN / 8;
    constexpr int NP = NT / 2;
    constexpr int OUTM = DUAL ? HDIM : MROWS;
    constexpr int ABYTES = 128 * SA * 2;
    constexpr int SM_AHI = 4096;
    constexpr int SM_ALO = SM_AHI + ABYTES;
    constexpr int SM_BHI = SM_ALO + ABYTES;
    constexpr int SM_BLO = SM_BHI + MROWS * SA * 2;
    constexpr int CH = K / 8;               // 8-float chunks per row
    constexpr int IT = (128 * CH) / 512;    // fill items per thread (2 or 4)
    constexpr int PF = 2;                   // prefetched items per thread

    extern __shared__ char smem[];
    const uint32_t sb = smem_u32(smem);
    float* sbuf = (float*)smem;
    float* avsh = (float*)(smem + 2048);

    const int tid  = threadIdx.x;
    const int wid  = tid >> 5;
    const int lane = tid & 31;
    const int wm   = wid & 3;
    const int wn   = wid >> 2;

    if (DUAL) {
        if (tid < 256) avsh[tid] = (tid < 128) ? av1[tid] : av2[tid - 128];
    } else if (BIAS) {
        if (tid < MROWS) avsh[tid] = bias[tid];
    }

    // ---- fill B once (resident across tiles) ----
    for (int i = tid; i < MROWS * CH; i += 512) {
        int r = i / CH, c = i % CH;
        size_t idx = ((size_t)r * K) / 8 + c;
        int so = (r * SA + c * 8) * 2;
        *(uint4*)(smem + SM_BHI + so) = ((const uint4*)Bhi)[idx];
        *(uint4*)(smem + SM_BLO + so) = ((const uint4*)Blo)[idx];
    }

    // item address helpers (item j of this thread -> i = tid + j*512)
    auto ldItem = [&](int rowBase, int j, uint4& x0, uint4& x1) {
        int i = tid + j * 512;
        int r = i / CH, c = i % CH;
        int gr = rowBase + r;
        x0 = make_uint4(0u, 0u, 0u, 0u);
        x1 = make_uint4(0u, 0u, 0u, 0u);
        if (gr < N) {
            size_t idx = (size_t)gr * (K / 4) + (size_t)c * 2;
            x0 = ((const uint4*)A)[idx];
            x1 = ((const uint4*)A)[idx + 1];
        }
    };
    auto stItem = [&](int j, uint4 x0, uint4 x1) {
        int i = tid + j * 512;
        int r = i / CH, c = i % CH;
        float f[8];
        *(uint4*)(f)     = x0;
        *(uint4*)(f + 4) = x1;
        uint4 vh, vl;
        split8(f, vh, vl);
        int so = (r * SA + c * 8) * 2;
        *(uint4*)(smem + SM_AHI + so) = vh;
        *(uint4*)(smem + SM_ALO + so) = vl;
    };

    int arow[2], brow[NP];
#pragma unroll
    for (int mt = 0; mt < 2; mt++)
        arow[mt] = (wm * 32 + mt * 16 + (lane & 15)) * SA + ((lane >> 4) << 3);
#pragma unroll
    for (int np = 0; np < NP; np++)
        brow[np] = (wn * WN + np * 16 + (lane & 7) + ((lane >> 4) << 3)) * SA
                 + (((lane >> 3) & 1) << 3);

    // prefetch first tile (overlaps B-fill LDGs above)
    uint4 pf0[PF], pf1[PF];
    if (blockIdx.x < nTiles) {
#pragma unroll
        for (int j = 0; j < PF; j++)
            ldItem(blockIdx.x * 128, j, pf0[j], pf1[j]);
    }

    for (int tile = blockIdx.x; tile < nTiles; tile += gridDim.x) {
        const int rowBase = tile * 128;
        __syncthreads();   // prev-iter consumers done (B-fill done on iter 0)

        // ---- store prefetched items; load+store the rest ----
#pragma unroll
        for (int j = 0; j < PF; j++) stItem(j, pf0[j], pf1[j]);
#pragma unroll
        for (int j = PF; j < IT; j++) {
            uint4 a0, a1;
            ldItem(rowBase, j, a0, a1);
            stItem(j, a0, a1);
        }
        __syncthreads();

        // ---- issue prefetch for next tile (drains under MMA loop) ----
        {
            int ntile = tile + gridDim.x;
            if (ntile < nTiles) {
#pragma unroll
                for (int j = 0; j < PF; j++)
                    ldItem(ntile * 128, j, pf0[j], pf1[j]);
            }
        }

        float acc[2][NT][4];
#pragma unroll
        for (int mt = 0; mt < 2; mt++)
#pragma unroll
            for (int nt = 0; nt < NT; nt++) {
                acc[mt][nt][0] = 0.f; acc[mt][nt][1] = 0.f;
                acc[mt][nt][2] = 0.f; acc[mt][nt][3] = 0.f;
            }

        // ---- merged mainloop: per k-step, ahi/alo once; Bhi + Blo streamed
#pragma unroll
        for (int k0 = 0; k0 < K; k0 += 16) {
            uint32_t ahi[2][4], alo[2][4];
#pragma unroll
            for (int mt = 0; mt < 2; mt++) {
                ldsm_x4(ahi[mt], sb + SM_AHI + (uint32_t)(arow[mt] + k0) * 2);
                ldsm_x4(alo[mt], sb + SM_ALO + (uint32_t)(arow[mt] + k0) * 2);
            }
#pragma unroll
            for (int np = 0; np < NP; np++) {
                uint32_t th[4], tl[4];
                ldsm_x4(th, sb + SM_BHI + (uint32_t)(brow[np] + k0) * 2);
                ldsm_x4(tl, sb + SM_BLO + (uint32_t)(brow[np] + k0) * 2);
#pragma unroll
                for (int mt = 0; mt < 2; mt++) {
                    mma_bf16(acc[mt][np * 2],     ahi[mt], th);
                    mma_bf16(acc[mt][np * 2 + 1], ahi[mt], th + 2);
                    mma_bf16(acc[mt][np * 2],     alo[mt], th);
                    mma_bf16(acc[mt][np * 2 + 1], alo[mt], th + 2);
                    mma_bf16(acc[mt][np * 2],     ahi[mt], tl);
                    mma_bf16(acc[mt][np * 2 + 1], ahi[mt], tl + 2);
                }
            }
        }

        // ---- epilogue ----
        if (DUAL) {
            const int half = wn >> 1;
            const int cb   = (wn & 1) * 64;
            float* Yo = half ? Y2 : Y1;
            const float* av = avsh + half * 128;
#pragma unroll
            for (int mt = 0; mt < 2; mt++) {
                int r0 = wm * 32 + mt * 16 + (lane >> 2);
                int gr0 = rowBase + r0, gr1 = gr0 + 8;
                float p0 = 0.f, p1 = 0.f;
#pragma unroll
                for (int nt = 0; nt < NT; nt++) {
                    int lc = cb + nt * 8 + (lane & 3) * 2;
                    float v0 = acc[mt][nt][0], v1 = acc[mt][nt][1];
                    float v2 = acc[mt][nt][2], v3 = acc[mt][nt][3];
                    if (gr0 < N) *(float2*)(Yo + (size_t)gr0 * HDIM + lc) = make_float2(v0, v1);
                    if (gr1 < N) *(float2*)(Yo + (size_t)gr1 * HDIM + lc) = make_float2(v2, v3);
                    p0 = fmaf(v0, av[lc], fmaf(v1, av[lc + 1], p0));
                    p1 = fmaf(v2, av[lc], fmaf(v3, av[lc + 1], p1));
                }
                p0 += __shfl_xor_sync(0xffffffffu, p0, 1);
                p0 += __shfl_xor_sync(0xffffffffu, p0, 2);
                p1 += __shfl_xor_sync(0xffffffffu, p1, 1);
                p1 += __shfl_xor_sync(0xffffffffu, p1, 2);
                if ((lane & 3) == 0) {
                    sbuf[wn * 128 + r0]     = p0;
                    sbuf[wn * 128 + r0 + 8] = p1;
                }
            }
            __syncthreads();
            for (int i = tid; i < 256; i += 512) {
                int row = i & 127, h = i >> 7;
                int gr = rowBase + row;
                if (gr < N)
                    (h ? s2 : s1)[gr] = sbuf[h * 256 + row] + sbuf[h * 256 + 128 + row];
            }
        } else {
#pragma unroll
            for (int mt = 0; mt < 2; mt++) {
                int r0 = wm * 32 + mt * 16 + (lane >> 2);
                int gr0 = rowBase + r0, gr1 = gr0 + 8;
#pragma unroll
                for (int nt = 0; nt < NT; nt++) {
                    int cc = wn * WN + nt * 8 + (lane & 3) * 2;
                    float b0 = BIAS ? avsh[cc] : 0.f, b1 = BIAS ? avsh[cc + 1] : 0.f;
                    float v0 = acc[mt][nt][0] + b0, v1 = acc[mt][nt][1] + b1;
                    float v2 = acc[mt][nt][2] + b0, v3 = acc[mt][nt][3] + b1;
                    if (gr0 < N) *(float2*)(Y1 + (size_t)gr0 * OUTM + cc) = make_float2(v0, v1);
                    if (gr1 < N) *(float2*)(Y1 + (size_t)gr1 * OUTM + cc) = make_float2(v2, v3);
                }
            }
        }
    }
}

// ---------------------------------------------------------------------------
// batched weight transpose+split
// ---------------------------------------------------------------------------
struct WBatch { const float* w[10]; int K[10]; int M[10]; int dst[10]; };

__global__ void wconv_all(WBatch wb, __nv_bfloat16* __restrict__ hi,
                          __nv_bfloat16* __restrict__ lo)
{
    int tid = blockIdx.x * blockDim.x + threadIdx.x;
    int wdx = tid >> 14;
    int i   = tid & 16383;
    if (wdx >= 10) return;
    int K = wb.K[wdx], M = wb.M[wdx];
    if (i >= K * M) return;
    int k = i / M, m = i % M;
    float w = wb.w[wdx][i];
    __nv_bfloat16 h = __float2bfloat16(w);
    int o = wb.dst[wdx] + m * K + k;
    hi[o] = h;
    lo[o] = __float2bfloat16(w - __bfloat162float(h));
}

// ---------------------------------------------------------------------------
// CSR build kernels (validated r4-r9)
// ---------------------------------------------------------------------------
__global__ void hist_kernel(const int* __restrict__ ti, int* __restrict__ cnt, int E)
{
    int e = blockIdx.x * blockDim.x + threadIdx.x;
    if (e < E) atomicAdd(cnt + __ldg(ti + e), 1);
}

__global__ void scan_partial(const int* __restrict__ cnt, int* __restrict__ bsum, int N)
{
    __shared__ int ws[8];
    int i = blockIdx.x * 256 + threadIdx.x;
    int v = (i < N) ? cnt[i] : 0;
#pragma unroll
    for (int o = 16; o; o >>= 1) v += __shfl_xor_sync(0xffffffffu, v, o);
    int lane = threadIdx.x & 31, wid = threadIdx.x >> 5;
    if (lane == 0) ws[wid] = v;
    __syncthreads();
    if (threadIdx.x == 0) {
        int t = 0;
#pragma unroll
        for (int j = 0; j < 8; j++) t += ws[j];
        bsum[blockIdx.x] = t;
    }
}

__global__ void scan_block_par(int* __restrict__ bsum, int nb)
{
    __shared__ int ws[16];
    int tid = threadIdx.x, lane = tid & 31, w = tid >> 5;
    int v = (tid < nb) ? bsum[tid] : 0;
    int x = v;
#pragma unroll
    for (int o = 1; o < 32; o <<= 1) {
        int y = __shfl_up_sync(0xffffffffu, x, o);
        if (lane >= o) x += y;
    }
    if (lane == 31) ws[w] = x;
    __syncthreads();
    if (w == 0 && lane < 16) {
        int q = ws[lane], sx = q;
#pragma unroll
        for (int o = 1; o < 16; o <<= 1) {
            int y = __shfl_up_sync(0x0000ffffu, sx, o);
            if (lane >= o) sx += y;
        }
        ws[lane] = sx - q;
    }
    __syncthreads();
    if (tid < nb) bsum[tid] = (x - v) + ws[w];
}

__global__ void scan_final(const int* __restrict__ cnt, const int* __restrict__ bsum,
                           int* __restrict__ rowptr, int* __restrict__ cur, int N, int E)
{
    __shared__ int ws[8];
    int i = blockIdx.x * 256 + threadIdx.x;
    int lane = threadIdx.x & 31, wid = threadIdx.x >> 5;
    int v = (i < N) ? cnt[i] : 0;
    int x = v;
#pragma unroll
    for (int o = 1; o < 32; o <<= 1) {
        int y = __shfl_up_sync(0xffffffffu, x, o);
        if (lane >= o) x += y;
    }
    if (lane == 31) ws[wid] = x;
    __syncthreads();
    if (wid == 0) {
        int w = (lane < 8) ? ws[lane] : 0;
        int sx = w;
#pragma unroll
        for (int o = 1; o < 8; o <<= 1) {
            int y = __shfl_up_sync(0xffffffffu, sx, o);
            if (lane >= o) sx += y;
        }
        if (lane < 8) ws[lane] = sx - w;
    }
    __syncthreads();
    int excl = (x - v) + ws[wid] + bsum[blockIdx.x];
    if (i < N) { rowptr[i] = excl; cur[i] = excl; }
    if (i == N - 1) rowptr[N] = excl + v;
}

__global__ void scatter_kernel(const int* __restrict__ si, const int* __restrict__ ti,
                               int* __restrict__ cur, int* __restrict__ s2s, int E)
{
    int e = blockIdx.x * blockDim.x + threadIdx.x;
    if (e >= E) return;
    int s1 = __ldg(si + e);
    int s2 = __ldg(si + s1);           // faithful src[si][si]
    int t  = __ldg(ti + e);
    int pos = atomicAdd(cur + t, 1);
    s2s[pos] = s2;
}

// ---------------------------------------------------------------------------
// fused aggregation + finalize: warp per target (validated r4-r9)
// ---------------------------------------------------------------------------
__global__ void agg_kernel(const int* __restrict__ rowptr, const int* __restrict__ s2s,
                           const float* __restrict__ src, const float* __restrict__ tgt,
                           const float* __restrict__ ssrc, const float* __restrict__ stgt,
                           float* __restrict__ out, int Ntgt)
{
    int t    = (blockIdx.x * blockDim.x + threadIdx.x) >> 5;
    int lane = threadIdx.x & 31;
    if (t >= Ntgt) return;

    int start = __ldg(rowptr + t), end = __ldg(rowptr + t + 1);
    float stt = __ldg(stgt + t);

    float4 acc = make_float4(0.f, 0.f, 0.f, 0.f);
    float dsum = 0.f;

    for (int base = start; base < end; base += 32) {
        int n = min(32, end - base);
        int sid = 0; float att = 0.f;
        if (lane < n) {
            sid = __ldg(s2s + base + lane);
            float logit = __ldg(ssrc + sid) + stt;
            float lr = logit > 0.f ? logit : LEAK * logit;
            att = expf(lr);
            dsum += att;
        }
        int j = 0;
        for (; j + 4 <= n; j += 4) {
            int   s0 = __shfl_sync(0xffffffffu, sid, j);
            int   s1 = __shfl_sync(0xffffffffu, sid, j + 1);
            int   s2 = __shfl_sync(0xffffffffu, sid, j + 2);
            int   s3 = __shfl_sync(0xffffffffu, sid, j + 3);
            float a0 = __shfl_sync(0xffffffffu, att, j);
            float a1 = __shfl_sync(0xffffffffu, att, j + 1);
            float a2 = __shfl_sync(0xffffffffu, att, j + 2);
            float a3 = __shfl_sync(0xffffffffu, att, j + 3);
            float4 v0 = __ldg((const float4*)src + (size_t)s0 * 32 + lane);
            float4 v1 = __ldg((const float4*)src + (size_t)s1 * 32 + lane);
            float4 v2 = __ldg((const float4*)src + (size_t)s2 * 32 + lane);
            float4 v3 = __ldg((const float4*)src + (size_t)s3 * 32 + lane);
            acc.x = fmaf(a0, v0.x, fmaf(a1, v1.x, fmaf(a2, v2.x, fmaf(a3, v3.x, acc.x))));
            acc.y = fmaf(a0, v0.y, fmaf(a1, v1.y, fmaf(a2, v2.y, fmaf(a3, v3.y, acc.y))));
            acc.z = fmaf(a0, v0.z, fmaf(a1, v1.z, fmaf(a2, v2.z, fmaf(a3, v3.z, acc.z))));
            acc.w = fmaf(a0, v0.w, fmaf(a1, v1.w, fmaf(a2, v2.w, fmaf(a3, v3.w, acc.w))));
        }
        for (; j < n; j++) {
            int   sj = __shfl_sync(0xffffffffu, sid, j);
            float aj = __shfl_sync(0xffffffffu, att, j);
            float4 v = __ldg((const float4*)src + (size_t)sj * 32 + lane);
            acc.x = fmaf(aj, v.x, acc.x);
            acc.y = fmaf(aj, v.y, acc.y);
            acc.z = fmaf(aj, v.z, acc.z);
            acc.w = fmaf(aj, v.w, acc.w);
        }
    }
#pragma unroll
    for (int o = 16; o; o >>= 1) dsum += __shfl_xor_sync(0xffffffffu, dsum, o);

    float inv = 1.f / (dsum + EPS_C);
    float4 tg = __ldg((const float4*)tgt + (size_t)t * 32 + lane);
    float4 o;
    o.x = fmaxf(fmaf(acc.x, inv, tg.x), 0.f);
    o.y = fmaxf(fmaf(acc.y, inv, tg.y), 0.f);
    o.z = fmaxf(fmaf(acc.z, inv, tg.z), 0.f);
    o.w = fmaxf(fmaf(acc.w, inv, tg.w), 0.f);
    ((float4*)out)[(size_t)t * 32 + lane] = o;
}

// ---------------------------------------------------------------------------
// host driver
// ---------------------------------------------------------------------------
template<int K>
static void launch_dual(const float* A, const __nv_bfloat16* Bhi, const __nv_bfloat16* Blo,
                        const float* av1, const float* av2,
                        float* Y1, float* Y2, float* s1, float* s2, int N,
                        cudaStream_t st)
{
    constexpr size_t smemsz = 4096 + 2 * (size_t)(128 * (K + 8) * 2)
                                   + 2 * (size_t)(256 * (K + 8) * 2);
    cudaFuncSetAttribute(mma_core<K, 256, true, false>,
                         cudaFuncAttributeMaxDynamicSharedMemorySize, (int)smemsz);
    int tiles = (N + 127) / 128;
    int grid  = tiles < 148 ? tiles : 148;
    mma_core<K, 256, true, false><<<grid, 512, smemsz, st>>>(
        A, Bhi, Blo, av1, av2, nullptr, Y1, Y2, s1, s2, N, tiles);
}

static void launch_final(const float* A, const __nv_bfloat16* Bhi, const __nv_bfloat16* Blo,
                         const float* bias, float* Y, int N, cudaStream_t st)
{
    constexpr size_t smemsz = 4096 + 2 * (size_t)(128 * 136 * 2)
                                   + 2 * (size_t)(64 * 136 * 2);
    cudaFuncSetAttribute(mma_core<128, 64, false, true>,
                         cudaFuncAttributeMaxDynamicSharedMemorySize, (int)smemsz);
    int tiles = (N + 127) / 128;
    int grid  = tiles < 148 ? tiles : 148;
    mma_core<128, 64, false, true><<<grid, 512, smemsz, st>>>(
        A, Bhi, Blo, nullptr, nullptr, bias, Y, nullptr, nullptr, nullptr, N, tiles);
}

static void build_csr(const int* si, const int* ti, int E, int Ntgt,
                      int* cnt, int* cur, int* bsum, int* rowptr, int* s2s,
                      cudaStream_t st)
{
    cudaMemsetAsync(cnt, 0, (size_t)Ntgt * sizeof(int), st);
    hist_kernel<<<(E + 255) / 256, 256, 0, st>>>(ti, cnt, E);
    int nb = (Ntgt + 255) / 256;
    scan_partial<<<nb, 256, 0, st>>>(cnt, bsum, Ntgt);
    scan_block_par<<<1, 512, 0, st>>>(bsum, nb);
    scan_final<<<nb, 256, 0, st>>>(cnt, bsum, rowptr, cur, Ntgt, E);
    scatter_kernel<<<(E + 255) / 256, 256, 0, st>>>(si, ti, cur, s2s, E);
}

extern "C" void kernel_launch(void* const* d_in, const int* in_sizes, int n_in,
                              void* d_out, int out_size)
{
    const float* x_user = (const float*)d_in[0];
    const float* x_spot = (const float*)d_in[1];
    const int*   e_us   = (const int*)d_in[2];
    const int*   e_su   = (const int*)d_in[3];
    const float* a_us0 = (const float*)d_in[6];
    const float* a_su0 = (const float*)d_in[9];
    const float* a_us1 = (const float*)d_in[12];
    const float* a_su1 = (const float*)d_in[15];
    const float* b_ou  = (const float*)d_in[17];
    const float* b_os  = (const float*)d_in[19];

    const int N_USER = in_sizes[0] / 64;
    const int N_SPOT = in_sizes[1] / 64;
    const int E      = in_sizes[2] / 2;

    const int* si_us = e_us;
    const int* ti_us = e_us + E;
    const int* si_su = e_su;
    const int* ti_su = e_su + E;

    float *pA, *pB, *pC, *pD, *pA2, *pB2, *pC2, *pD2, *p_xu1, *p_xs1;
    float *p_ssu, *p_stu, *p_sss, *p_sts, *p_ssu2, *p_stu2, *p_sss2, *p_sts2;
    int *p_s2us, *p_s2su, *p_rpus, *p_rpsu, *p_cnt, *p_cur, *p_bsum;
    __nv_bfloat16 *p_wh, *p_wl;
    cudaGetSymbolAddress((void**)&pA, g_A);
    cudaGetSymbolAddress((void**)&pB, g_B);
    cudaGetSymbolAddress((void**)&pC, g_C);
    cudaGetSymbolAddress((void**)&pD, g_D);
    cudaGetSymbolAddress((void**)&pA2, g_A2);
    cudaGetSymbolAddress((void**)&pB2, g_B2);
    cudaGetSymbolAddress((void**)&pC2, g_C2);
    cudaGetSymbolAddress((void**)&pD2, g_D2);
    cudaGetSymbolAddress((void**)&p_xu1, g_xu1);
    cudaGetSymbolAddress((void**)&p_xs1, g_xs1);
    cudaGetSymbolAddress((void**)&p_ssu, g_ssu);
    cudaGetSymbolAddress((void**)&p_stu, g_stu);
    cudaGetSymbolAddress((void**)&p_sss, g_sss);
    cudaGetSymbolAddress((void**)&p_sts, g_sts);
    cudaGetSymbolAddress((void**)&p_ssu2, g_ssu2);
    cudaGetSymbolAddress((void**)&p_stu2, g_stu2);
    cudaGetSymbolAddress((void**)&p_sss2, g_sss2);
    cudaGetSymbolAddress((void**)&p_sts2, g_sts2);
    cudaGetSymbolAddress((void**)&p_s2us, g_s2s_us);
    cudaGetSymbolAddress((void**)&p_s2su, g_s2s_su);
    cudaGetSymbolAddress((void**)&p_rpus, g_rp_us);
    cudaGetSymbolAddress((void**)&p_rpsu, g_rp_su);
    cudaGetSymbolAddress((void**)&p_cnt, g_cnt);
    cudaGetSymbolAddress((void**)&p_cur, g_cur);
    cudaGetSymbolAddress((void**)&p_bsum, g_bsum);
    cudaGetSymbolAddress((void**)&p_wh, g_wh);
    cudaGetSymbolAddress((void**)&p_wl, g_wl);

    float* out_xu = (float*)d_out;
    float* out_xs = out_xu + (size_t)N_USER * HDIM;
    float* out_ou = out_xs + (size_t)N_SPOT * HDIM;
    float* out_os = out_ou + (size_t)N_USER * 64;

    // fork stream + events
    cudaStream_t sf;
    cudaStreamCreateWithFlags(&sf, cudaStreamNonBlocking);
    cudaEvent_t eStart, eU, eB, eSu, eGu, eGs, eA2, eEnd;
    cudaEventCreateWithFlags(&eStart, cudaEventDisableTiming);
    cudaEventCreateWithFlags(&eU, cudaEventDisableTiming);
    cudaEventCreateWithFlags(&eB, cudaEventDisableTiming);
    cudaEventCreateWithFlags(&eSu, cudaEventDisableTiming);
    cudaEventCreateWithFlags(&eGu, cudaEventDisableTiming);
    cudaEventCreateWithFlags(&eGs, cudaEventDisableTiming);
    cudaEventCreateWithFlags(&eA2, cudaEventDisableTiming);
    cudaEventCreateWithFlags(&eEnd, cudaEventDisableTiming);

    // ---- fork ----
    cudaEventRecord(eStart, 0);
    cudaStreamWaitEvent(sf, eStart, 0);

    // side: CSR builds (under the L0 GEMMs)
    build_csr(si_us, ti_us, E, N_SPOT, p_cnt, p_cur, p_bsum, p_rpus, p_s2us, sf);
    cudaEventRecord(eU, sf);
    build_csr(si_su, ti_su, E, N_USER, p_cnt, p_cur, p_bsum, p_rpsu, p_s2su, sf);

    // main: weights + layer-0 GEMMs
    {
        WBatch wb;
        const float* src[10] = {
            (const float*)d_in[4],  (const float*)d_in[8],
            (const float*)d_in[5],  (const float*)d_in[7],
            (const float*)d_in[10], (const float*)d_in[14],
            (const float*)d_in[11], (const float*)d_in[13],
            (const float*)d_in[16], (const float*)d_in[18]
        };
        const int Ks[10]  = {64, 64, 64, 64, 128, 128, 128, 128, 128, 128};
        const int Ms[10]  = {128, 128, 128, 128, 128, 128, 128, 128, 64, 64};
        const int Ds[10]  = {0, 8192, 16384, 24576, 32768, 49152,
                             65536, 81920, 98304, 106496};
        for (int i = 0; i < 10; i++) {
            wb.w[i] = src[i]; wb.K[i] = Ks[i]; wb.M[i] = Ms[i]; wb.dst[i] = Ds[i];
        }
        wconv_all<<<(10 * 16384) / 256, 256>>>(wb, p_wh, p_wl);
    }
    launch_dual<64>(x_user, p_wh + 0, p_wl + 0, a_us0, a_su0 + HDIM,
                    pA, pD, p_ssu, p_sts, N_USER, 0);
    launch_dual<64>(x_spot, p_wh + 16384, p_wl + 16384, a_us0 + HDIM, a_su0,
                    pB, pC, p_stu, p_sss, N_SPOT, 0);
    cudaEventRecord(eB, 0);

    const int AGG_T = 256;
    auto aggGrid = [&](int n) { return (n * 32 + AGG_T - 1) / AGG_T; };

    // side: agg_su alone (full BW) -> G128(xu1)
    cudaStreamWaitEvent(sf, eB, 0);
    agg_kernel<<<aggGrid(N_USER), AGG_T, 0, sf>>>(p_rpsu, p_s2su, pC, pD,
                                                  p_sss, p_sts, p_xu1, N_USER);
    cudaEventRecord(eSu, sf);
    launch_dual<128>(p_xu1, p_wh + 32768, p_wl + 32768, a_us1, a_su1 + HDIM,
                     pA2, pD2, p_ssu2, p_sts2, N_USER, sf);
    cudaEventRecord(eGu, sf);

    // main: agg_us staggered to overlap G128(xu1); then G128(xs1)
    cudaStreamWaitEvent(0, eU, 0);
    cudaStreamWaitEvent(0, eSu, 0);
    agg_kernel<<<aggGrid(N_SPOT), AGG_T>>>(p_rpus, p_s2us, pA, pB,
                                           p_ssu, p_stu, p_xs1, N_SPOT);
    launch_dual<128>(p_xs1, p_wh + 65536, p_wl + 65536, a_us1 + HDIM, a_su1,
                     pB2, pC2, p_stu2, p_sss2, N_SPOT, 0);
    cudaEventRecord(eGs, 0);

    // main: agg_us2 (needs both L1 GEMMs) -> final_s
    cudaStreamWaitEvent(0, eGu, 0);
    agg_kernel<<<aggGrid(N_SPOT), AGG_T>>>(p_rpus, p_s2us, pA2, pB2,
                                           p_ssu2, p_stu2, out_xs, N_SPOT);
    cudaEventRecord(eA2, 0);
    launch_final(out_xs, p_wh + 106496, p_wl + 106496, b_os, out_os, N_SPOT, 0);

    // side: agg_su2 staggered to overlap final_s -> final_u
    cudaStreamWaitEvent(sf, eGs, 0);
    cudaStreamWaitEvent(sf, eA2, 0);
    agg_kernel<<<aggGrid(N_USER), AGG_T, 0, sf>>>(p_rpsu, p_s2su, pC2, pD2,
                                                  p_sss2, p_sts2, out_xu, N_USER);
    launch_final(out_xu, p_wh + 98304, p_wl + 98304, b_ou, out_ou, N_USER, sf);
    cudaEventRecord(eEnd, sf);

    // ---- join ----
    cudaStreamWaitEvent(0, eEnd, 0);
}